// round 8
// baseline (speedup 1.0000x reference)
#include <cuda_runtime.h>
#include <cstdint>

#define CD 512
#define KD 65536
#define NPAIRS 10
#define SPLITS 14
#define NCHUNK 2048
#define ASTRIDE 36
#define TILEF (128 * ASTRIDE)
#define CHUNKF (2 * TILEF)                 // 9216 floats per chunk (A+B)
#define FMA_BASE (3 * CHUNKF)              // fma ring after tensor's 3 stages
#define SMEM_BYTES (6 * CHUNKF * 4)        // 221184 B -> 1 CTA/SM

typedef unsigned long long u64;

__device__ float g_scratch[(size_t)SPLITS * CD * CD];

__device__ __forceinline__ uint32_t s2u(const void* p) {
    uint32_t a;
    asm("{ .reg .u64 t; cvta.to.shared.u64 t, %1; cvt.u32.u64 %0, t; }" : "=r"(a) : "l"(p));
    return a;
}
__device__ __forceinline__ uint32_t cvt_tf32(float x) {
    uint32_t r; asm("cvt.rna.tf32.f32 %0, %1;" : "=r"(r) : "f"(x)); return r;
}
__device__ __forceinline__ void cp16(uint32_t dst, const float* src) {
    asm volatile("cp.async.cg.shared.global [%0], [%1], 16;" :: "r"(dst), "l"(src) : "memory");
}
__device__ __forceinline__ u64 pk2(float lo, float hi) {
    u64 r; asm("mov.b64 %0, {%1, %2};" : "=l"(r) : "f"(lo), "f"(hi)); return r;
}
__device__ __forceinline__ void unpk2(float& lo, float& hi, u64 v) {
    asm("mov.b64 {%0, %1}, %2;" : "=f"(lo), "=f"(hi) : "l"(v));
}
__device__ __forceinline__ void fma2(u64& d, u64 a, u64 b) {
    asm("fma.rn.f32x2 %0, %1, %2, %0;" : "+l"(d) : "l"(a), "l"(b));
}
__device__ __forceinline__ void mma_t(float* d, const uint32_t* a, const uint32_t* b) {
    asm volatile(
        "mma.sync.aligned.m16n8k8.row.col.f32.tf32.tf32.f32 "
        "{%0,%1,%2,%3}, {%4,%5,%6,%7}, {%8,%9}, {%0,%1,%2,%3};"
        : "+f"(d[0]), "+f"(d[1]), "+f"(d[2]), "+f"(d[3])
        : "r"(a[0]), "r"(a[1]), "r"(a[2]), "r"(a[3]), "r"(b[0]), "r"(b[1]));
}
__device__ __forceinline__ float getc(const float4& v, int ke) {
    return ke == 0 ? v.x : ke == 1 ? v.y : ke == 2 ? v.z : v.w;
}
__device__ __forceinline__ void barg(int id) {
    asm volatile("bar.sync %0, 128;" :: "r"(id) : "memory");
}

// 128 threads load chunk c (A tile + B tile) into ring slot at float-offset fbase.
__device__ __forceinline__ void load_chunk(uint32_t sb, uint32_t fbase, const float* gAt,
                                           const float* gBt, bool diag, int c, int r0, int sg) {
    const uint32_t base = sb + fbase * 4u;
    #pragma unroll
    for (int r8 = 0; r8 < 8; r8++) {
        uint32_t off = (uint32_t)((r0 + 16 * r8) * ASTRIDE + 4 * sg) * 4u;
        cp16(base + off, gAt + (size_t)(16 * r8) * KD + (size_t)c * 32);
        if (!diag)
            cp16(base + (uint32_t)TILEF * 4u + off, gBt + (size_t)(16 * r8) * KD + (size_t)c * 32);
    }
}

__device__ __forceinline__ void tchunk(const float* __restrict__ As, const float* __restrict__ Bs,
                                       int wid, int g, int t, float acc[2][16][4]) {
    #pragma unroll
    for (int kk = 0; kk < 4; kk++) {
        const int kc = kk * 8 + t;
        uint32_t ar[2][4];
        #pragma unroll
        for (int mi = 0; mi < 2; mi++) {
            const int r = 32 * wid + 16 * mi + g;
            ar[mi][0] = cvt_tf32(As[r * ASTRIDE + kc]);
            ar[mi][1] = cvt_tf32(As[(r + 8) * ASTRIDE + kc]);
            ar[mi][2] = cvt_tf32(As[r * ASTRIDE + kc + 4]);
            ar[mi][3] = cvt_tf32(As[(r + 8) * ASTRIDE + kc + 4]);
        }
        uint32_t br[16][2];
        #pragma unroll
        for (int ni = 0; ni < 16; ni++) {
            const int nn = 8 * ni + g;
            br[ni][0] = cvt_tf32(Bs[nn * ASTRIDE + kc]);
            br[ni][1] = cvt_tf32(Bs[nn * ASTRIDE + kc + 4]);
        }
        #pragma unroll
        for (int mi = 0; mi < 2; mi++)
            #pragma unroll
            for (int ni = 0; ni < 16; ni++)
                mma_t(acc[mi][ni], ar[mi], br[ni]);
    }
}

// fma warp: rows R0+8*tr+rr (rr<8), cols tc+64h+16q(+8). acc[rr][4h+q]=(lo,hi) col pair.
__device__ __forceinline__ void fchunk(const float* __restrict__ As, const float* __restrict__ Bs,
                                       int R0, int tr, int tc, u64 acc[8][8]) {
    #pragma unroll
    for (int kb = 0; kb < 8; kb++) {
        float4 a4[8];
        #pragma unroll
        for (int rr = 0; rr < 8; rr++)
            a4[rr] = *(const float4*)(As + (R0 + 8 * tr + rr) * ASTRIDE + 4 * kb);
        #pragma unroll
        for (int h = 0; h < 2; h++) {
            float4 b4[8];
            #pragma unroll
            for (int jj = 0; jj < 8; jj++)
                b4[jj] = *(const float4*)(Bs + (tc + 64 * h + 8 * jj) * ASTRIDE + 4 * kb);
            #pragma unroll
            for (int ke = 0; ke < 4; ke++) {
                u64 bp[4];
                #pragma unroll
                for (int q = 0; q < 4; q++)
                    bp[q] = pk2(getc(b4[2 * q], ke), getc(b4[2 * q + 1], ke));
                #pragma unroll
                for (int rr = 0; rr < 8; rr++) {
                    const float av = getc(a4[rr], ke);
                    const u64 ad = pk2(av, av);
                    #pragma unroll
                    for (int q = 0; q < 4; q++) fma2(acc[rr][4 * h + q], ad, bp[q]);
                }
            }
        }
    }
}

__device__ __forceinline__ int tch(int c0, int i) { return c0 + 11 * (i >> 3) + (i & 7); }
__device__ __forceinline__ int fch(int c0, int i) { return c0 + 11 * (i / 3) + 8 + (i % 3); }

__global__ __launch_bounds__(256, 1) void gram_hyb(const float* __restrict__ X) {
    extern __shared__ float smem[];
    const uint32_t sb = s2u(smem);

    const int pair = blockIdx.x % NPAIRS, split = blockIdx.x / NPAIRS;
    int bi = 0;
    while ((bi + 1) * (bi + 2) / 2 <= pair) bi++;
    const int bj = pair - bi * (bi + 1) / 2;
    const bool diag = (bi == bj);

    const int c0 = (split * NCHUNK) / SPLITS, c1 = ((split + 1) * NCHUNK) / SPLITS;
    const int n = c1 - c0, g11 = n / 11, rem = n % 11;

    const int tid = threadIdx.x, lane = tid & 31, wid = tid >> 5;
    const int u = tid & 127, r0 = u >> 3, sg = u & 7;
    const float* gAt = X + (size_t)(bi * 128 + r0) * KD + sg * 4;
    const float* gBt = X + (size_t)(bj * 128 + r0) * KD + sg * 4;

    float tacc[2][16][4];

    if (wid < 4) {                       // ---- tensor group ----
        const int cnt = 8 * g11 + (rem < 8 ? rem : 8);
        const int g = lane >> 2, t = lane & 3;
        #pragma unroll
        for (int mi = 0; mi < 2; mi++)
            #pragma unroll
            for (int ni = 0; ni < 16; ni++)
                #pragma unroll
                for (int e = 0; e < 4; e++) tacc[mi][ni][e] = 0.f;
        #pragma unroll
        for (int s = 0; s < 2; s++) {
            if (s < cnt) load_chunk(sb, (uint32_t)(s * CHUNKF), gAt, gBt, diag, tch(c0, s), r0, sg);
            asm volatile("cp.async.commit_group;" ::: "memory");
        }
        for (int i = 0; i < cnt; i++) {
            asm volatile("cp.async.wait_group 1;" ::: "memory");
            barg(1);
            if (i + 2 < cnt)
                load_chunk(sb, (uint32_t)(((i + 2) % 3) * CHUNKF), gAt, gBt, diag, tch(c0, i + 2), r0, sg);
            asm volatile("cp.async.commit_group;" ::: "memory");
            const float* As = smem + (i % 3) * CHUNKF;
            tchunk(As, diag ? As : As + TILEF, wid, g, t, tacc);
        }
    } else {                             // ---- FFMA2 group ----
        int cf = rem - 8; cf = cf < 0 ? 0 : (cf > 3 ? 3 : cf);
        const int cnt = 3 * g11 + cf;
        const int R0 = 32 * (wid - 4), tr = lane >> 3, tc = lane & 7;
        u64 facc[8][8];
        #pragma unroll
        for (int rr = 0; rr < 8; rr++)
            #pragma unroll
            for (int p = 0; p < 8; p++) facc[rr][p] = pk2(0.f, 0.f);
        #pragma unroll
        for (int s = 0; s < 2; s++) {
            if (s < cnt) load_chunk(sb, (uint32_t)(FMA_BASE + s * CHUNKF), gAt, gBt, diag, fch(c0, s), r0, sg);
            asm volatile("cp.async.commit_group;" ::: "memory");
        }
        for (int i = 0; i < cnt; i++) {
            asm volatile("cp.async.wait_group 1;" ::: "memory");
            barg(2);
            if (i + 2 < cnt)
                load_chunk(sb, (uint32_t)(FMA_BASE + ((i + 2) % 3) * CHUNKF), gAt, gBt, diag, fch(c0, i + 2), r0, sg);
            asm volatile("cp.async.commit_group;" ::: "memory");
            const float* As = smem + FMA_BASE + (i % 3) * CHUNKF;
            fchunk(As, diag ? As : As + TILEF, R0, tr, tc, facc);
        }
        // stash partials in (own) fma ring area, stride 130
        float* mg = smem + FMA_BASE;
        #pragma unroll
        for (int rr = 0; rr < 8; rr++) {
            const int row = R0 + 8 * tr + rr;
            #pragma unroll
            for (int p = 0; p < 8; p++) {
                float lo, hi; unpk2(lo, hi, facc[rr][p]);
                const int cl = tc + 64 * (p >> 2) + 16 * (p & 3);
                mg[row * 130 + cl] = lo;
                mg[row * 130 + cl + 8] = hi;
            }
        }
    }
    __syncthreads();

    if (wid < 4) {                       // merge + write split partial
        const int g = lane >> 2, t = lane & 3;
        const float* mg = smem + FMA_BASE;
        float* out = g_scratch + (size_t)split * CD * CD;
        #pragma unroll
        for (int mi = 0; mi < 2; mi++) {
            const int r = 32 * wid + 16 * mi + g;
            #pragma unroll
            for (int ni = 0; ni < 16; ni++) {
                const int c = 8 * ni + 2 * t;
                const float2 m0 = *(const float2*)(mg + r * 130 + c);
                const float2 m1 = *(const float2*)(mg + (r + 8) * 130 + c);
                const size_t gi = (size_t)(bi * 128 + r), gj = (size_t)(bj * 128 + c);
                *(float2*)(out + gi * CD + gj) =
                    make_float2(tacc[mi][ni][0] + m0.x, tacc[mi][ni][1] + m0.y);
                *(float2*)(out + (gi + 8) * CD + gj) =
                    make_float2(tacc[mi][ni][2] + m1.x, tacc[mi][ni][3] + m1.y);
            }
        }
    }
}

__global__ void gram_reduce(float* __restrict__ out) {
    const int idx = blockIdx.x * blockDim.x + threadIdx.x;
    const int i = idx >> 9, j = idx & 511;
    if (j > i) return;
    float s = 0.f;
    #pragma unroll
    for (int sp = 0; sp < SPLITS; ++sp)
        s += g_scratch[(size_t)sp * CD * CD + idx];
    out[(size_t)i * CD + j] = s;
    out[(size_t)j * CD + i] = s;
}

extern "C" void kernel_launch(void* const* d_in, const int* in_sizes, int n_in,
                              void* d_out, int out_size) {
    const float* x = (const float*)d_in[0];   // [512, 65536]
    float* out = (float*)d_out;               // [512, 512]
    cudaFuncSetAttribute(gram_hyb, cudaFuncAttributeMaxDynamicSharedMemorySize, SMEM_BYTES);
    gram_hyb<<<NPAIRS * SPLITS, 256, SMEM_BYTES>>>(x);
    gram_reduce<<<(CD * CD) / 256, 256>>>(out);
}

// round 9
// speedup vs baseline: 2.8800x; 2.8800x over previous
#include <cuda_runtime.h>
#include <cstdint>

#define CD 512
#define KD 65536
#define BM 128
#define BK 32
#define NPAIRS 10                    // 4x4 lower-triangle tile pairs
#define SPLITS 29
#define NCHUNK (KD / BK)             // 2048
#define NSTAGE 3
#define ASTRIDE 36                   // floats per smem row
#define TILE_FLOATS (BM * ASTRIDE)
#define STAGE_FLOATS (2 * TILE_FLOATS)
#define SMEM_BYTES (NSTAGE * STAGE_FLOATS * 4)   // 110592 -> 2 CTAs/SM

// Deterministic split-K scratch (no device allocation allowed)
__device__ float g_scratch[(size_t)SPLITS * CD * CD];

__device__ __forceinline__ uint32_t s2u(const void* p) {
    uint32_t a;
    asm("{ .reg .u64 t; cvta.to.shared.u64 t, %1; cvt.u32.u64 %0, t; }" : "=r"(a) : "l"(p));
    return a;
}

// pack two f32 (lo = k, hi = k+1) to bf16x2 with round-to-nearest (unbiased)
__device__ __forceinline__ uint32_t bf2(float2 v) {
    uint32_t r;
    asm("cvt.rn.bf16x2.f32 %0, %1, %2;" : "=r"(r) : "f"(v.y), "f"(v.x));
    return r;
}

__device__ __forceinline__ void cp16(uint32_t dst, const float* src) {
    asm volatile("cp.async.cg.shared.global [%0], [%1], 16;" :: "r"(dst), "l"(src) : "memory");
}

__global__ __launch_bounds__(128, 2) void gram_mma(const float* __restrict__ X) {
    extern __shared__ float smem[];
    const uint32_t sb = s2u(smem);

    const int pair  = blockIdx.x % NPAIRS;
    const int split = blockIdx.x / NPAIRS;

    int bi = 0;
    while ((bi + 1) * (bi + 2) / 2 <= pair) bi++;
    const int bj = pair - bi * (bi + 1) / 2;

    const int c0 = (split * NCHUNK) / SPLITS;
    const int c1 = ((split + 1) * NCHUNK) / SPLITS;

    const int tid  = threadIdx.x;
    const int lane = tid & 31;
    const int wid  = tid >> 5;
    const int wr   = wid >> 1;          // 0..1 -> rows 64*wr
    const int wc   = wid & 1;           // 0..1 -> cols 64*wc
    const int g    = lane >> 2;         // 0..7
    const int t    = lane & 3;          // 0..3

    // loader mapping (identical to R4): 128 threads, both tiles
    const int ldr  = tid >> 3;          // 0..15
    const int lds_ = tid & 7;           // 0..7
    const float* gA = X + (size_t)(bi * BM + ldr) * KD + lds_ * 4;
    const float* gB = X + (size_t)(bj * BM + ldr) * KD + lds_ * 4;

    float acc[4][8][4];
    #pragma unroll
    for (int mi = 0; mi < 4; mi++)
        #pragma unroll
        for (int ni = 0; ni < 8; ni++)
            #pragma unroll
            for (int e = 0; e < 4; e++) acc[mi][ni][e] = 0.f;

    const int niters = c1 - c0;

    // ---- prologue: issue stages 0..NSTAGE-2 ----
    #pragma unroll
    for (int s = 0; s < NSTAGE - 1; s++) {
        if (s < niters) {
            const int c = c0 + s;
            const uint32_t base = sb + (uint32_t)(s * STAGE_FLOATS) * 4u;
            #pragma unroll
            for (int r8 = 0; r8 < 8; r8++) {
                uint32_t doff = (uint32_t)((ldr + r8 * 16) * ASTRIDE + lds_ * 4) * 4u;
                cp16(base + doff, gA + (size_t)(r8 * 16) * KD + (size_t)c * BK);
                cp16(base + (uint32_t)(TILE_FLOATS * 4) + doff,
                     gB + (size_t)(r8 * 16) * KD + (size_t)c * BK);
            }
        }
        asm volatile("cp.async.commit_group;" ::: "memory");
    }

    for (int i = 0; i < niters; i++) {
        asm volatile("cp.async.wait_group %0;" :: "n"(NSTAGE - 2) : "memory");
        __syncthreads();

        // issue stage i+NSTAGE-1
        {
            const int cn = c0 + i + NSTAGE - 1;
            if (cn < c1) {
                const int st = (i + NSTAGE - 1) % NSTAGE;
                const uint32_t base = sb + (uint32_t)(st * STAGE_FLOATS) * 4u;
                #pragma unroll
                for (int r8 = 0; r8 < 8; r8++) {
                    uint32_t doff = (uint32_t)((ldr + r8 * 16) * ASTRIDE + lds_ * 4) * 4u;
                    cp16(base + doff, gA + (size_t)(r8 * 16) * KD + (size_t)cn * BK);
                    cp16(base + (uint32_t)(TILE_FLOATS * 4) + doff,
                         gB + (size_t)(r8 * 16) * KD + (size_t)cn * BK);
                }
            }
            asm volatile("cp.async.commit_group;" ::: "memory");
        }

        // compute stage i%NSTAGE: 2 k-steps of K=16 (bf16 m16n8k16)
        const float* As = smem + (i % NSTAGE) * STAGE_FLOATS;
        const float* Bs = As + TILE_FLOATS;

        #pragma unroll
        for (int kk = 0; kk < 2; kk++) {
            const int kb = kk * 16;
            uint32_t ar[4][4];
            #pragma unroll
            for (int mi = 0; mi < 4; mi++) {
                const int r = 64 * wr + 16 * mi + g;
                ar[mi][0] = bf2(*(const float2*)(As + r * ASTRIDE + kb + 2 * t));
                ar[mi][1] = bf2(*(const float2*)(As + (r + 8) * ASTRIDE + kb + 2 * t));
                ar[mi][2] = bf2(*(const float2*)(As + r * ASTRIDE + kb + 2 * t + 8));
                ar[mi][3] = bf2(*(const float2*)(As + (r + 8) * ASTRIDE + kb + 2 * t + 8));
            }
            uint32_t br[8][2];
            #pragma unroll
            for (int ni = 0; ni < 8; ni++) {
                const int n = 64 * wc + 8 * ni + g;
                br[ni][0] = bf2(*(const float2*)(Bs + n * ASTRIDE + kb + 2 * t));
                br[ni][1] = bf2(*(const float2*)(Bs + n * ASTRIDE + kb + 2 * t + 8));
            }
            #pragma unroll
            for (int mi = 0; mi < 4; mi++)
                #pragma unroll
                for (int ni = 0; ni < 8; ni++) {
                    asm volatile(
                        "mma.sync.aligned.m16n8k16.row.col.f32.bf16.bf16.f32 "
                        "{%0,%1,%2,%3}, {%4,%5,%6,%7}, {%8,%9}, {%0,%1,%2,%3};"
                        : "+f"(acc[mi][ni][0]), "+f"(acc[mi][ni][1]),
                          "+f"(acc[mi][ni][2]), "+f"(acc[mi][ni][3])
                        : "r"(ar[mi][0]), "r"(ar[mi][1]), "r"(ar[mi][2]), "r"(ar[mi][3]),
                          "r"(br[ni][0]), "r"(br[ni][1]));
                }
        }
    }

    // epilogue: write 128x128 fp32 partial tile to scratch
    float* out = g_scratch + (size_t)split * CD * CD;
    #pragma unroll
    for (int mi = 0; mi < 4; mi++) {
        const int gi = bi * BM + 64 * wr + 16 * mi + g;
        #pragma unroll
        for (int ni = 0; ni < 8; ni++) {
            const int gj = bj * BM + 64 * wc + 8 * ni + 2 * t;
            *(float2*)(out + (size_t)gi * CD + gj)       = make_float2(acc[mi][ni][0], acc[mi][ni][1]);
            *(float2*)(out + (size_t)(gi + 8) * CD + gj) = make_float2(acc[mi][ni][2], acc[mi][ni][3]);
        }
    }
}

__global__ void gram_reduce(float* __restrict__ out) {
    const int idx = blockIdx.x * blockDim.x + threadIdx.x;
    const int i = idx >> 9;
    const int j = idx & 511;
    if (j > i) return;
    float s = 0.f;
    #pragma unroll 8
    for (int sp = 0; sp < SPLITS; ++sp)
        s += g_scratch[(size_t)sp * CD * CD + idx];
    out[(size_t)i * CD + j] = s;
    out[(size_t)j * CD + i] = s;
}

extern "C" void kernel_launch(void* const* d_in, const int* in_sizes, int n_in,
                              void* d_out, int out_size) {
    const float* x = (const float*)d_in[0];   // [1,512,256,256] = [512, 65536]
    float* out = (float*)d_out;               // [1,1,512,512]

    cudaFuncSetAttribute(gram_mma, cudaFuncAttributeMaxDynamicSharedMemorySize, SMEM_BYTES);
    gram_mma<<<NPAIRS * SPLITS, 128, SMEM_BYTES>>>(x);
    gram_reduce<<<(CD * CD) / 256, 256>>>(out);
}

// round 11
// speedup vs baseline: 5.5607x; 1.9308x over previous
#include <cuda_runtime.h>
#include <cstdint>

#define CD 512
#define KD 65536
#define BM 128
#define BK 64
#define NPAIRS 10                    // 4x4 lower-triangle tile pairs
#define SPLITS 15
#define NCHUNK (KD / BK)             // 1024
#define NSTAGE 3
#define WSTRIDE 36                   // 32-bit words per smem row (conflict-free: bank=4g+t+c)
#define TILE_W (BM * WSTRIDE)        // 4608 words per tile
#define STAGE_W (2 * TILE_W)
#define SMEM_BYTES (NSTAGE * STAGE_W * 4)   // 110592 -> 2 CTAs/SM

// Deterministic split-K scratch + bf16 copy of X (no device allocation allowed)
__device__ float g_scratch[(size_t)SPLITS * CD * CD];
__device__ uint32_t g_xw[(size_t)CD * KD / 2];      // X as bf16 pairs (64 MB)

__device__ __forceinline__ uint32_t s2u(const void* p) {
    uint32_t a;
    asm("{ .reg .u64 t; cvta.to.shared.u64 t, %1; cvt.u32.u64 %0, t; }" : "=r"(a) : "l"(p));
    return a;
}

// pack (lo=x, hi=y) into bf16x2 with round-to-nearest (unbiased)
__device__ __forceinline__ uint32_t bf2(float x, float y) {
    uint32_t r;
    asm("cvt.rn.bf16x2.f32 %0, %1, %2;" : "=r"(r) : "f"(y), "f"(x));
    return r;
}

__device__ __forceinline__ void cp16(uint32_t dst, const void* src) {
    asm volatile("cp.async.cg.shared.global [%0], [%1], 16;" :: "r"(dst), "l"(src) : "memory");
}

// ---- pre-convert: fp32 X -> bf16 pairs (memory-bound) ----
__global__ void to_bf16(const float* __restrict__ X) {
    const size_t i = (size_t)blockIdx.x * blockDim.x + threadIdx.x;   // 0 .. CD*KD/8-1
    const float4* p = (const float4*)X + 2 * i;
    float4 a = p[0], b = p[1];
    uint4 w;
    w.x = bf2(a.x, a.y); w.y = bf2(a.z, a.w);
    w.z = bf2(b.x, b.y); w.w = bf2(b.z, b.w);
    ((uint4*)g_xw)[i] = w;
}

__global__ __launch_bounds__(128, 2) void gram_mma() {
    extern __shared__ uint32_t smw[];
    const uint32_t sb = s2u(smw);

    const int pair  = blockIdx.x % NPAIRS;
    const int split = blockIdx.x / NPAIRS;

    int bi = 0;
    while ((bi + 1) * (bi + 2) / 2 <= pair) bi++;
    const int bj = pair - bi * (bi + 1) / 2;
    const bool diag = (bi == bj);

    const int c0 = (split * NCHUNK) / SPLITS;
    const int c1 = ((split + 1) * NCHUNK) / SPLITS;

    const int tid  = threadIdx.x;
    const int lane = tid & 31;
    const int wid  = tid >> 5;
    const int wr   = wid >> 1;          // 0..1 -> rows 64*wr
    const int wc   = wid & 1;           // 0..1 -> cols 64*wc
    const int g    = lane >> 2;         // 0..7
    const int t    = lane & 3;          // 0..3

    // loader: bf16 rows; per tile 128 rows x 8 granules(16B=8k); 8 cp16/thread/tile
    const int ldr = tid >> 3;           // 0..15 (+16*r8)
    const int g16 = tid & 7;            // 16B granule (8 k-values)
    const char* gA = (const char*)g_xw + ((size_t)(bi * BM + ldr) * KD + g16 * 8) * 2;
    const char* gB = (const char*)g_xw + ((size_t)(bj * BM + ldr) * KD + g16 * 8) * 2;

    float acc[4][8][4];
    #pragma unroll
    for (int mi = 0; mi < 4; mi++)
        #pragma unroll
        for (int ni = 0; ni < 8; ni++)
            #pragma unroll
            for (int e = 0; e < 4; e++) acc[mi][ni][e] = 0.f;

    const int niters = c1 - c0;

    // ---- prologue ----
    #pragma unroll
    for (int s = 0; s < NSTAGE - 1; s++) {
        if (s < niters) {
            const int c = c0 + s;
            const uint32_t base = sb + (uint32_t)(s * STAGE_W) * 4u;
            #pragma unroll
            for (int r8 = 0; r8 < 8; r8++) {
                const uint32_t woff = (uint32_t)((ldr + 16 * r8) * WSTRIDE + 4 * g16) * 4u;
                cp16(base + woff, gA + ((size_t)(16 * r8) * KD + (size_t)c * BK) * 2);
                if (!diag)
                    cp16(base + (uint32_t)(TILE_W * 4) + woff,
                         gB + ((size_t)(16 * r8) * KD + (size_t)c * BK) * 2);
            }
        }
        asm volatile("cp.async.commit_group;" ::: "memory");
    }

    for (int i = 0; i < niters; i++) {
        asm volatile("cp.async.wait_group %0;" :: "n"(NSTAGE - 2) : "memory");
        __syncthreads();

        {
            const int cn = c0 + i + NSTAGE - 1;
            if (cn < c1) {
                const int st = (i + NSTAGE - 1) % NSTAGE;
                const uint32_t base = sb + (uint32_t)(st * STAGE_W) * 4u;
                #pragma unroll
                for (int r8 = 0; r8 < 8; r8++) {
                    const uint32_t woff = (uint32_t)((ldr + 16 * r8) * WSTRIDE + 4 * g16) * 4u;
                    cp16(base + woff, gA + ((size_t)(16 * r8) * KD + (size_t)cn * BK) * 2);
                    if (!diag)
                        cp16(base + (uint32_t)(TILE_W * 4) + woff,
                             gB + ((size_t)(16 * r8) * KD + (size_t)cn * BK) * 2);
                }
            }
            asm volatile("cp.async.commit_group;" ::: "memory");
        }

        // compute: 4 k-steps of K=16 bf16 mma; frags are direct word loads (conflict-free)
        const uint32_t* As = smw + (i % NSTAGE) * STAGE_W;
        const uint32_t* Bs = diag ? As : (As + TILE_W);

        #pragma unroll
        for (int kk = 0; kk < 4; kk++) {
            const int kw = kk * 8 + t;      // word index of k-pair (k=2t..) within row
            uint32_t ar[4][4];
            #pragma unroll
            for (int mi = 0; mi < 4; mi++) {
                const int r = 64 * wr + 16 * mi + g;
                ar[mi][0] = As[r * WSTRIDE + kw];
                ar[mi][1] = As[(r + 8) * WSTRIDE + kw];
                ar[mi][2] = As[r * WSTRIDE + kw + 4];
                ar[mi][3] = As[(r + 8) * WSTRIDE + kw + 4];
            }
            uint32_t br[8][2];
            #pragma unroll
            for (int ni = 0; ni < 8; ni++) {
                const int n = 64 * wc + 8 * ni + g;
                br[ni][0] = Bs[n * WSTRIDE + kw];
                br[ni][1] = Bs[n * WSTRIDE + kw + 4];
            }
            #pragma unroll
            for (int mi = 0; mi < 4; mi++)
                #pragma unroll
                for (int ni = 0; ni < 8; ni++) {
                    asm volatile(
                        "mma.sync.aligned.m16n8k16.row.col.f32.bf16.bf16.f32 "
                        "{%0,%1,%2,%3}, {%4,%5,%6,%7}, {%8,%9}, {%0,%1,%2,%3};"
                        : "+f"(acc[mi][ni][0]), "+f"(acc[mi][ni][1]),
                          "+f"(acc[mi][ni][2]), "+f"(acc[mi][ni][3])
                        : "r"(ar[mi][0]), "r"(ar[mi][1]), "r"(ar[mi][2]), "r"(ar[mi][3]),
                          "r"(br[ni][0]), "r"(br[ni][1]));
                }
        }
    }

    // epilogue: write 128x128 fp32 partial tile to scratch
    float* out = g_scratch + (size_t)split * CD * CD;
    #pragma unroll
    for (int mi = 0; mi < 4; mi++) {
        const int gi = bi * BM + 64 * wr + 16 * mi + g;
        #pragma unroll
        for (int ni = 0; ni < 8; ni++) {
            const int gj = bj * BM + 64 * wc + 8 * ni + 2 * t;
            *(float2*)(out + (size_t)gi * CD + gj)       = make_float2(acc[mi][ni][0], acc[mi][ni][1]);
            *(float2*)(out + (size_t)(gi + 8) * CD + gj) = make_float2(acc[mi][ni][2], acc[mi][ni][3]);
        }
    }
}

__global__ void gram_reduce(float* __restrict__ out) {
    const int idx = blockIdx.x * blockDim.x + threadIdx.x;
    const int i = idx >> 9;
    const int j = idx & 511;
    if (j > i) return;
    float s = 0.f;
    #pragma unroll
    for (int sp = 0; sp < SPLITS; ++sp)
        s += g_scratch[(size_t)sp * CD * CD + idx];
    out[(size_t)i * CD + j] = s;
    out[(size_t)j * CD + i] = s;
}

extern "C" void kernel_launch(void* const* d_in, const int* in_sizes, int n_in,
                              void* d_out, int out_size) {
    const float* x = (const float*)d_in[0];   // [1,512,256,256] = [512, 65536]
    float* out = (float*)d_out;               // [1,1,512,512]

    to_bf16<<<(int)((size_t)CD * KD / 8 / 256), 256>>>(x);
    cudaFuncSetAttribute(gram_mma, cudaFuncAttributeMaxDynamicSharedMemorySize, SMEM_BYTES);
    gram_mma<<<NPAIRS * SPLITS, 128, SMEM_BYTES>>>();
    gram_reduce<<<(CD * CD) / 256, 256>>>(out);
}

// round 12
// speedup vs baseline: 6.3284x; 1.1381x over previous
#include <cuda_runtime.h>
#include <cstdint>

#define CD 512
#define KD 65536
#define BM 128
#define BK 64
#define NPAIRS 10                    // 4x4 lower-triangle tile pairs
#define SPLITS 14
#define NCHUNK (KD / BK)             // 1024
#define NSLOT 3
#define WSTRIDE 36                   // 32-bit words per smem row (frag LDS conflict-free)
#define TILE_W (BM * WSTRIDE)        // 4608 words per bf16 tile (128 rows x 64 k)
#define STAGE_W (2 * TILE_W)
#define SMEM_BYTES (NSLOT * STAGE_W * 4)   // 110592 B

// Deterministic split-K scratch (no device allocation allowed)
__device__ float g_scratch[(size_t)SPLITS * CD * CD];

__device__ __forceinline__ uint32_t s2u(const void* p) {
    uint32_t a;
    asm("{ .reg .u64 t; cvta.to.shared.u64 t, %1; cvt.u32.u64 %0, t; }" : "=r"(a) : "l"(p));
    return a;
}

// pack (lo=x, hi=y) into bf16x2, round-to-nearest (unbiased)
__device__ __forceinline__ uint32_t bf2(float x, float y) {
    uint32_t r;
    asm("cvt.rn.bf16x2.f32 %0, %1, %2;" : "=r"(r) : "f"(y), "f"(x));
    return r;
}

__device__ __forceinline__ void sts64(uint32_t a, uint32_t w0, uint32_t w1) {
    asm volatile("st.shared.v2.b32 [%0], {%1, %2};" :: "r"(a), "r"(w0), "r"(w1) : "memory");
}

__device__ __forceinline__ void bar_wait(int id) {
    asm volatile("bar.sync %0, 256;" :: "r"(id) : "memory");
}
__device__ __forceinline__ void bar_post(int id) {
    asm volatile("bar.arrive %0, 256;" :: "r"(id) : "memory");
}

__global__ __launch_bounds__(256, 1) void gram_fused(const float* __restrict__ X) {
    extern __shared__ uint32_t smw[];
    const uint32_t sb = s2u(smw);

    const int pair  = blockIdx.x % NPAIRS;
    const int split = blockIdx.x / NPAIRS;

    int bi = 0;
    while ((bi + 1) * (bi + 2) / 2 <= pair) bi++;
    const int bj = pair - bi * (bi + 1) / 2;
    const bool diag = (bi == bj);

    const int c0 = (split * NCHUNK) / SPLITS;
    const int c1 = ((split + 1) * NCHUNK) / SPLITS;
    const int niters = c1 - c0;

    const int tid  = threadIdx.x;
    const int lane = tid & 31;
    const int wid  = tid >> 5;

    if (wid >= 4) {
        // ================= producer warps (4-7): fp32 LDG -> cvt -> STS =================
        const int pu    = tid - 128;        // 0..127
        const int ptile = pu >> 6;          // 0 = A tile, 1 = B tile
        const int pv    = pu & 63;
        const int pg    = pv & 15;          // float4 granule: k = 4*pg .. 4*pg+3
        const int prb   = pv >> 4;          // row base 0..3 (rows prb + 4*kidx)
        const bool skip = diag && (ptile == 1);
        const uint32_t tile_w = (uint32_t)(ptile ? TILE_W : 0);
        const float* gp = X + (size_t)((ptile ? bj : bi) * BM + prb) * KD + 4 * pg;

        for (int i = 0; i < niters; i++) {
            const int s = i % NSLOT;
            if (i >= NSLOT) bar_wait(4 + s);          // wait slot empty
            if (!skip) {
                const float* g = gp + (size_t)(c0 + i) * BK;
                const uint32_t base = sb + (uint32_t)(s * STAGE_W + tile_w) * 4u;
                #pragma unroll
                for (int b = 0; b < 2; b++) {
                    float4 v[16];
                    #pragma unroll
                    for (int k = 0; k < 16; k++)
                        v[k] = *(const float4*)(g + (size_t)(4 * (16 * b + k)) * KD);
                    #pragma unroll
                    for (int k = 0; k < 16; k++) {
                        const int row = prb + 4 * (16 * b + k);
                        sts64(base + (uint32_t)(row * WSTRIDE + 2 * pg) * 4u,
                              bf2(v[k].x, v[k].y), bf2(v[k].z, v[k].w));
                    }
                }
            }
            bar_post(1 + s);                          // signal slot full
        }
        return;
    }

    // ================= consumer warps (0-3): bf16 m16n8k16 mma =================
    const int wr = wid >> 1;            // 0..1 -> rows 64*wr
    const int wc = wid & 1;             // 0..1 -> cols 64*wc
    const int g  = lane >> 2;           // 0..7
    const int t  = lane & 3;            // 0..3

    float acc[4][8][4];
    #pragma unroll
    for (int mi = 0; mi < 4; mi++)
        #pragma unroll
        for (int ni = 0; ni < 8; ni++)
            #pragma unroll
            for (int e = 0; e < 4; e++) acc[mi][ni][e] = 0.f;

    for (int i = 0; i < niters; i++) {
        const int s = i % NSLOT;
        bar_wait(1 + s);                              // wait slot full

        const uint32_t* As = smw + s * STAGE_W;
        const uint32_t* Bs = diag ? As : (As + TILE_W);

        #pragma unroll
        for (int kk = 0; kk < 4; kk++) {
            const int kw = kk * 8 + t;
            uint32_t ar[4][4];
            #pragma unroll
            for (int mi = 0; mi < 4; mi++) {
                const int r = 64 * wr + 16 * mi + g;
                ar[mi][0] = As[r * WSTRIDE + kw];
                ar[mi][1] = As[(r + 8) * WSTRIDE + kw];
                ar[mi][2] = As[r * WSTRIDE + kw + 4];
                ar[mi][3] = As[(r + 8) * WSTRIDE + kw + 4];
            }
            uint32_t br[8][2];
            #pragma unroll
            for (int ni = 0; ni < 8; ni++) {
                const int n = 64 * wc + 8 * ni + g;
                br[ni][0] = Bs[n * WSTRIDE + kw];
                br[ni][1] = Bs[n * WSTRIDE + kw + 4];
            }
            #pragma unroll
            for (int mi = 0; mi < 4; mi++)
                #pragma unroll
                for (int ni = 0; ni < 8; ni++) {
                    asm volatile(
                        "mma.sync.aligned.m16n8k16.row.col.f32.bf16.bf16.f32 "
                        "{%0,%1,%2,%3}, {%4,%5,%6,%7}, {%8,%9}, {%0,%1,%2,%3};"
                        : "+f"(acc[mi][ni][0]), "+f"(acc[mi][ni][1]),
                          "+f"(acc[mi][ni][2]), "+f"(acc[mi][ni][3])
                        : "r"(ar[mi][0]), "r"(ar[mi][1]), "r"(ar[mi][2]), "r"(ar[mi][3]),
                          "r"(br[ni][0]), "r"(br[ni][1]));
                }
        }
        bar_post(4 + s);                              // signal slot empty
    }

    // epilogue: write 128x128 fp32 partial tile to scratch (consumers only)
    float* out = g_scratch + (size_t)split * CD * CD;
    #pragma unroll
    for (int mi = 0; mi < 4; mi++) {
        const int gi = bi * BM + 64 * wr + 16 * mi + g;
        #pragma unroll
        for (int ni = 0; ni < 8; ni++) {
            const int gj = bj * BM + 64 * wc + 8 * ni + 2 * t;
            *(float2*)(out + (size_t)gi * CD + gj)       = make_float2(acc[mi][ni][0], acc[mi][ni][1]);
            *(float2*)(out + (size_t)(gi + 8) * CD + gj) = make_float2(acc[mi][ni][2], acc[mi][ni][3]);
        }
    }
}

__global__ void gram_reduce(float* __restrict__ out) {
    const int idx = blockIdx.x * blockDim.x + threadIdx.x;
    const int i = idx >> 9;
    const int j = idx & 511;
    if (j > i) return;
    float s = 0.f;
    #pragma unroll
    for (int sp = 0; sp < SPLITS; ++sp)
        s += g_scratch[(size_t)sp * CD * CD + idx];
    out[(size_t)i * CD + j] = s;
    out[(size_t)j * CD + i] = s;
}

extern "C" void kernel_launch(void* const* d_in, const int* in_sizes, int n_in,
                              void* d_out, int out_size) {
    const float* x = (const float*)d_in[0];   // [1,512,256,256] = [512, 65536]
    float* out = (float*)d_out;               // [1,1,512,512]

    cudaFuncSetAttribute(gram_fused, cudaFuncAttributeMaxDynamicSharedMemorySize, SMEM_BYTES);
    gram_fused<<<NPAIRS * SPLITS, 256, SMEM_BYTES>>>(x);
    gram_reduce<<<(CD * CD) / 256, 256>>>(out);
}